// round 4
// baseline (speedup 1.0000x reference)
#include <cuda_runtime.h>
#include <cuda_bf16.h>

// Device-global accumulators (zero-initialized at module load; the last block
// resets them after each run so graph replays stay deterministic).
__device__ float g_ce_sum;
__device__ unsigned int g_ticket;

__global__ void ce_fused_kernel(const float* __restrict__ predicts,
                                const int* __restrict__ labels,
                                float* __restrict__ out,
                                int n, float inv_n) {
    const int tid0 = blockIdx.x * blockDim.x + threadIdx.x;
    const int n4 = n >> 2;  // full int4 label groups

    float local = 0.0f;

    // --- main vectorized part: 1 int4 label load + 4 independent gathers ---
    if (tid0 < n4) {
        const int4 lbl = __ldg(&((const int4*)labels)[tid0]);
        const size_t rb = (size_t)tid0 * 4u * 128u;
        float p0 = __ldcs(&predicts[rb + 0 * 128u + (unsigned)lbl.x]);
        float p1 = __ldcs(&predicts[rb + 1 * 128u + (unsigned)lbl.y]);
        float p2 = __ldcs(&predicts[rb + 2 * 128u + (unsigned)lbl.z]);
        float p3 = __ldcs(&predicts[rb + 3 * 128u + (unsigned)lbl.w]);
        local = __logf(p0) + __logf(p1) + __logf(p2) + __logf(p3);
    }

    // --- scalar tail (rows n4*4 .. n-1) ---
    const int tail = n - (n4 << 2);
    if (tid0 < tail) {
        const int row = (n4 << 2) + tid0;
        local += __logf(__ldcs(&predicts[(size_t)row * 128u + (unsigned)__ldg(&labels[row])]));
    }

    // --- warp reduce ---
#pragma unroll
    for (int o = 16; o > 0; o >>= 1)
        local += __shfl_xor_sync(0xffffffffu, local, o);

    // --- block reduce ---
    __shared__ float smem[32];
    const int lane = threadIdx.x & 31;
    const int wid = threadIdx.x >> 5;
    if (lane == 0) smem[wid] = local;
    __syncthreads();

    __shared__ bool s_last;
    if (wid == 0) {
        const int nwarps = blockDim.x >> 5;
        local = (lane < nwarps) ? smem[lane] : 0.0f;
#pragma unroll
        for (int o = 16; o > 0; o >>= 1)
            local += __shfl_xor_sync(0xffffffffu, local, o);
        if (lane == 0) {
            atomicAdd(&g_ce_sum, local);
            __threadfence();
            unsigned int old = atomicAdd(&g_ticket, 1u);
            s_last = (old == gridDim.x - 1);
        }
    }
    __syncthreads();

    // --- last block finalizes and resets for the next (graph replay) run ---
    if (s_last && threadIdx.x == 0) {
        __threadfence();
        float total = g_ce_sum;
        *out = -total * inv_n;
        g_ce_sum = 0.0f;
        g_ticket = 0u;
    }
}

extern "C" void kernel_launch(void* const* d_in, const int* in_sizes, int n_in,
                              void* d_out, int out_size) {
    // Identify inputs by element count: predicts has N*C elements, labels has N.
    int pi = 0, li = 1;
    if (n_in >= 2 && in_sizes[1] > in_sizes[0]) { pi = 1; li = 0; }

    const float* predicts = (const float*)d_in[pi];
    const int* labels = (const int*)d_in[li];
    float* out = (float*)d_out;

    const int n = in_sizes[li];

    constexpr int THREADS = 256;
    const int n4 = n >> 2;
    int blocks = (n4 + THREADS - 1) / THREADS;  // 1 int4 group per thread
    if (blocks < 1) blocks = 1;

    ce_fused_kernel<<<blocks, THREADS>>>(predicts, labels, out, n,
                                         1.0f / (float)n);
}